// round 8
// baseline (speedup 1.0000x reference)
#include <cuda_runtime.h>
#include <cstdint>

// Problem constants
#define NPTS   32768            // 32 * 32 * 32 points
#define DIM    64               // embedding dim
#define NE     1024             // codebook size
#define HW     1024             // 32*32 spatial
#define BHW    65536            // 64 channels * 1024 hw (per-batch stride in z)
#define PTSB   32               // points per block
#define NCH    16               // chunks of 64 codes
#define CCH    64               // codes per chunk
#define EPITCH 68               // padded es row pitch (floats), 272B = 16B aligned
#define NBLK   (NPTS / PTSB)    // 1024 blocks

// Output layout (flat concat of reference return tuple, float32):
// loss[1], z_q[2097152], perplexity[1], min_encodings[33554432], indices[32768]
#define OFF_LOSS 0ULL
#define OFF_ZQ   1ULL
#define OFF_PERP 2097153ULL
#define OFF_ENC  2097154ULL
#define OFF_IDX  35651586ULL

__device__ unsigned int d_count[NE];     // static-zero; finalize re-zeros
__device__ float        d_loss  = 0.f;   // finalize re-zeros
__device__ unsigned int d_done  = 0u;    // finalize re-zeros

// ---------------------------------------------------------------- helpers
struct __align__(16) ull2 { unsigned long long a, b; };

static __device__ __forceinline__ unsigned long long pk2(float v) {
    unsigned long long r;
    asm("mov.b64 %0, {%1,%2};" : "=l"(r) : "f"(v), "f"(v));
    return r;
}
static __device__ __forceinline__ void ffma2(unsigned long long& d,
                                             unsigned long long a,
                                             unsigned long long b) {
    asm("fma.rn.f32x2 %0, %1, %2, %0;" : "+l"(d) : "l"(a), "l"(b));
}
static __device__ __forceinline__ float2 upk(unsigned long long v) {
    float2 f;
    asm("mov.b64 {%0,%1}, %2;" : "=f"(f.x), "=f"(f.y) : "l"(v));
    return f;
}
static __device__ __forceinline__ unsigned int ordf(float x) {
    unsigned int b = __float_as_uint(x);
    return b ^ (unsigned int)(((int)b >> 31) | 0x80000000);
}
static __device__ __forceinline__ void cpasync16(unsigned int dst_smem,
                                                 const void* src) {
    asm volatile("cp.async.ca.shared.global [%0], [%1], 16;"
                 :: "r"(dst_smem), "l"(src));
}
#define CP_COMMIT() asm volatile("cp.async.commit_group;" ::: "memory")
#define CP_WAIT0()  asm volatile("cp.async.wait_group 0;" ::: "memory")

// ---------------------------------------------------------------- the single fused kernel
// block: 128 threads = 8 pt-groups (pt_t, 4 pts) x 16 code-groups (cg, 4 codes)
// block tile: 32 points x 64 codes per chunk (16 chunks -> 1024 codes)
// thread tile: 4 points (2 NATURAL f32x2 pairs) x 4 codes (pk2-duplicated)
//   acc[2][4] u64 = 32 regs; 8 ffma2 per k; es loaded straight from emb [c][k].
__global__ void __launch_bounds__(128, 4)
vq_main_kernel(const float* __restrict__ z, const float* __restrict__ emb,
               float* __restrict__ out)
{
    __shared__ __align__(16) float zs[DIM][PTSB];        // [k][pt] 8 KB
    __shared__ __align__(16) float es[2][CCH][EPITCH];   // [c][k] pad68, 34 KB
    __shared__ float zsq_s[PTSB];
    __shared__ float esq_s[CCH];
    __shared__ unsigned long long red[16][PTSB];         // 4 KB
    __shared__ float warp_s[4];
    __shared__ int   last_s;

    const int tid  = threadIdx.x;
    const int pt_t = tid & 7;     // 0..7  point group (4 pts)
    const int cg   = tid >> 3;    // 0..15 code group (4 codes)
    const int pt0  = blockIdx.x * PTSB;
    const int b    = pt0 >> 10;
    const int hw0  = pt0 & 1023;
    const float* zb = z + (size_t)b * BHW + hw0;

    // issue es chunk 0 fetch immediately (16 KB contiguous from emb)
    {
        unsigned int dst0 = (unsigned int)__cvta_generic_to_shared(&es[0][0][0]);
        #pragma unroll
        for (int i = 0; i < 8; ++i) {
            int f = i * 128 + tid;           // 16B unit 0..1023
            int c = f >> 4, k4 = f & 15;
            cpasync16(dst0 + (unsigned)(c * EPITCH + k4 * 4) * 4u,
                      emb + (size_t)c * DIM + k4 * 4);
        }
        CP_COMMIT();
    }

    // load z tile (coalesced), natural layout [k][pt]
    #pragma unroll
    for (int i = 0; i < 16; ++i) {
        int f = i * 128 + tid;
        int k = f >> 5, p = f & 31;
        zs[k][p] = zb[(size_t)k * HW + p];
    }

    // one-hot region head/tail scalars (base%4==2); float4 body interleaved below
    float* encb = out + OFF_ENC + (size_t)pt0 * NE;      // 32768 floats
    float4* e4  = (float4*)(encb + 2);                   // 8191 float4s
    if (tid == 0) {
        encb[0] = 0.f; encb[1] = 0.f;
        encb[32766] = 0.f; encb[32767] = 0.f;
    }
    __syncthreads();

    // per-point ||z||^2, sequential fp32 rn (matches reference rounding)
    if (tid < PTSB) {
        float s = 0.f;
        #pragma unroll
        for (int k = 0; k < DIM; ++k) {
            float v = zs[k][tid];
            s = __fadd_rn(s, __fmul_rn(v, v));
        }
        zsq_s[tid] = s;
    }

    unsigned long long best[4];
    #pragma unroll
    for (int p = 0; p < 4; ++p) best[p] = 0xFFFFFFFFFFFFFFFFULL;

    for (int h = 0; h < NCH; ++h) {
        const int buf = h & 1;
        CP_WAIT0();            // chunk h landed
        __syncthreads();       // visible to all; h-1 compute done

        // prefetch chunk h+1 into the other buffer
        if (h + 1 < NCH) {
            unsigned int dstn = (unsigned int)__cvta_generic_to_shared(
                &es[buf ^ 1][0][0]);
            const float* src = emb + (size_t)(h + 1) * CCH * DIM;
            #pragma unroll
            for (int i = 0; i < 8; ++i) {
                int f = i * 128 + tid;
                int c = f >> 4, k4 = f & 15;
                cpasync16(dstn + (unsigned)(c * EPITCH + k4 * 4) * 4u,
                          src + (size_t)c * DIM + k4 * 4);
            }
        }
        CP_COMMIT();

        // interleaved one-hot zero-fill slice (drains under the FMAs)
        #pragma unroll
        for (int i = 0; i < 4; ++i) {
            int j = h * 512 + i * 128 + tid;
            if (j < 8191) e4[j] = make_float4(0.f, 0.f, 0.f, 0.f);
        }

        // per-chunk ||e||^2, sequential fp32 rn (same order as before)
        if (tid < CCH) {
            float s = 0.f;
            #pragma unroll
            for (int k = 0; k < DIM; ++k) {
                float v = es[buf][tid][k];
                s = __fadd_rn(s, __fmul_rn(v, v));
            }
            esq_s[tid] = s;
        }
        __syncthreads();       // esq_s visible

        unsigned long long acc[2][4];      // [point-pair][code]
        #pragma unroll
        for (int pp = 0; pp < 2; ++pp)
            #pragma unroll
            for (int j = 0; j < 4; ++j) acc[pp][j] = 0ULL;

        #pragma unroll 8
        for (int k = 0; k < DIM; ++k) {
            ull2 zp = *(const ull2*)&zs[k][pt_t * 4];   // natural pairs {p0,p1},{p2,p3}
            #pragma unroll
            for (int j = 0; j < 4; ++j) {
                unsigned long long ed = pk2(es[buf][cg * 4 + j][k]);  // {e,e}
                ffma2(acc[0][j], zp.a, ed);
                ffma2(acc[1][j], zp.b, ed);
            }
        }

        // distances + running argmin (u64 key -> first-index tie-break)
        const int cbase = h * CCH + cg * 4;
        #pragma unroll
        for (int j = 0; j < 4; ++j) {
            float esq = esq_s[cg * 4 + j];
            unsigned code = (unsigned)(cbase + j);
            #pragma unroll
            for (int pp = 0; pp < 2; ++pp) {
                float2 dot = upk(acc[pp][j]);
                {
                    float zq2 = zsq_s[pt_t * 4 + 2 * pp];
                    float d = __fadd_rn(__fadd_rn(zq2, esq), -2.0f * dot.x);
                    unsigned long long k64 =
                        ((unsigned long long)ordf(d) << 32) | code;
                    if (k64 < best[2 * pp]) best[2 * pp] = k64;
                }
                {
                    float zq2 = zsq_s[pt_t * 4 + 2 * pp + 1];
                    float d = __fadd_rn(__fadd_rn(zq2, esq), -2.0f * dot.y);
                    unsigned long long k64 =
                        ((unsigned long long)ordf(d) << 32) | code;
                    if (k64 < best[2 * pp + 1]) best[2 * pp + 1] = k64;
                }
            }
        }
    }

    // cross-thread argmin reduction per point
    __syncthreads();
    #pragma unroll
    for (int p = 0; p < 4; ++p) red[cg][pt_t * 4 + p] = best[p];
    __syncthreads();

    if (tid < PTSB) {
        unsigned long long bk = red[0][tid];
        #pragma unroll
        for (int t = 1; t < 16; ++t) {
            unsigned long long v = red[t][tid];
            if (v < bk) bk = v;
        }
        int idx = (int)(unsigned int)bk;
        int n   = pt0 + tid;

        out[OFF_IDX + n] = (float)idx;
        atomicAdd(&d_count[idx], 1u);
        out[OFF_ENC + (unsigned long long)n * NE + (unsigned)idx] = 1.0f;

        // z_q gather + loss partial (straight-through: z_q_out == z_q in value)
        float errsum = 0.f;
        const float* er = emb + (size_t)idx * DIM;
        float* zq = out + OFF_ZQ + (size_t)b * BHW + hw0 + tid;
        #pragma unroll
        for (int c = 0; c < DIM; ++c) {
            float e  = __ldg(er + c);
            float zv = zs[c][tid];
            float df = e - zv;
            errsum   = fmaf(df, df, errsum);
            zq[(size_t)c * HW] = e;
        }
        #pragma unroll
        for (int o = 16; o > 0; o >>= 1)
            errsum += __shfl_down_sync(0xFFFFFFFFu, errsum, o);
        if (tid == 0) atomicAdd(&d_loss, errsum);
    }

    // ---------------- last-block finalize (perplexity + loss scalars) ----------------
    __threadfence();
    __syncthreads();
    if (tid == 0) last_s = (atomicAdd(&d_done, 1u) == NBLK - 1) ? 1 : 0;
    __syncthreads();
    if (last_s) {
        float part = 0.f;
        #pragma unroll
        for (int i = 0; i < 8; ++i) {
            int c = tid + i * 128;
            unsigned cnt = d_count[c];
            d_count[c] = 0u;                       // reset for graph replay
            float em = (float)cnt * (1.0f / 32768.0f);
            part += em * logf(em + 1e-10f);
        }
        #pragma unroll
        for (int o = 16; o > 0; o >>= 1)
            part += __shfl_down_sync(0xFFFFFFFFu, part, o);
        if ((tid & 31) == 0) warp_s[tid >> 5] = part;
        __syncthreads();
        if (tid == 0) {
            float w = warp_s[0] + warp_s[1] + warp_s[2] + warp_s[3];
            out[OFF_PERP] = expf(-w);
            out[OFF_LOSS] = 1.25f * d_loss * (1.0f / 2097152.0f);
            d_loss = 0.f;                          // reset for graph replay
            d_done = 0u;
        }
    }
}

// ---------------------------------------------------------------- launch
extern "C" void kernel_launch(void* const* d_in, const int* in_sizes, int n_in,
                              void* d_out, int out_size) {
    const float* z   = (const float*)d_in[0];
    const float* emb = (const float*)d_in[1];
    float*       out = (float*)d_out;

    vq_main_kernel<<<NBLK, 128>>>(z, emb, out);
}

// round 9
// speedup vs baseline: 1.0753x; 1.0753x over previous
#include <cuda_runtime.h>
#include <cstdint>

// Problem constants
#define NPTS   32768            // 32 * 32 * 32 points
#define DIM    64               // embedding dim
#define NE     1024             // codebook size
#define HW     1024             // 32*32 spatial
#define BHW    65536            // 64 channels * 1024 hw (per-batch stride in z)
#define PTSB   32               // points per block
#define CCH    64               // codes per chunk
#define NCH    16               // chunks
#define NBLK   (NPTS / PTSB)    // 1024 blocks

// Output layout (flat concat of reference return tuple, float32):
// loss[1], z_q[2097152], perplexity[1], min_encodings[33554432], indices[32768]
#define OFF_LOSS 0ULL
#define OFF_ZQ   1ULL
#define OFF_PERP 2097153ULL
#define OFF_ENC  2097154ULL
#define OFF_IDX  35651586ULL

__device__ float        d_esq[NE];
__device__ float        d_est[DIM * NE];   // transposed codebook [k][c]
__device__ unsigned int d_count[NE];
__device__ float        d_loss = 0.f;
__device__ unsigned int d_done = 0u;

// ---------------------------------------------------------------- helpers
struct __align__(16) ull2 { unsigned long long a, b; };

static __device__ __forceinline__ unsigned long long pk2(float v) {
    unsigned long long r;
    asm("mov.b64 %0, {%1,%2};" : "=l"(r) : "f"(v), "f"(v));
    return r;
}
static __device__ __forceinline__ void ffma2(unsigned long long& d,
                                             unsigned long long a,
                                             unsigned long long b) {
    asm("fma.rn.f32x2 %0, %1, %2, %0;" : "+l"(d) : "l"(a), "l"(b));
}
static __device__ __forceinline__ float2 upk(unsigned long long v) {
    float2 f;
    asm("mov.b64 {%0,%1}, %2;" : "=f"(f.x), "=f"(f.y) : "l"(v));
    return f;
}
static __device__ __forceinline__ unsigned int ordf(float x) {
    unsigned int b = __float_as_uint(x);
    return b ^ (unsigned int)(((int)b >> 31) | 0x80000000);
}
static __device__ __forceinline__ void cpasync16(unsigned int dst_smem,
                                                 const void* src) {
    asm volatile("cp.async.ca.shared.global [%0], [%1], 16;"
                 :: "r"(dst_smem), "l"(src));
}
#define CP_COMMIT() asm volatile("cp.async.commit_group;" ::: "memory")
#define CP_WAIT0()  asm volatile("cp.async.wait_group 0;" ::: "memory")

// ---------------------------------------------------------------- prep
// 16 blocks x 128 threads; block handles 64 codes. Verified ~5.3us.
__global__ void prep_kernel(const float* __restrict__ emb) {
    __shared__ float sb[64][DIM + 1];
    const int tid = threadIdx.x;
    const int c0  = blockIdx.x * 64;

    const float4* src = (const float4*)(emb + (size_t)c0 * DIM);
    #pragma unroll
    for (int i = 0; i < 8; ++i) {
        int f  = i * 128 + tid;
        int c  = f >> 4;
        int k4 = f & 15;
        float4 v = src[f];
        sb[c][k4 * 4 + 0] = v.x;
        sb[c][k4 * 4 + 1] = v.y;
        sb[c][k4 * 4 + 2] = v.z;
        sb[c][k4 * 4 + 3] = v.w;
    }
    __syncthreads();

    if (tid < 64) {
        const int c = c0 + tid;
        float s = 0.f;
        #pragma unroll
        for (int k = 0; k < DIM; ++k) {
            float v = sb[tid][k];
            s = __fadd_rn(s, __fmul_rn(v, v));
            d_est[k * NE + c] = v;
        }
        d_esq[c]   = s;
        d_count[c] = 0u;
        if (c == 0) { d_loss = 0.f; d_done = 0u; }
    }
}

// ---------------------------------------------------------------- main fused kernel
// block: 128 threads = 8 pt-groups (pt_t, 4 pts) x 16 code-groups (cg, 4 codes)
// block tile: 32 points x 64 codes per chunk (16 chunks -> 1024 codes)
// thread tile: 4 points x 4 codes (2 f32x2 code-pairs) -> acc[4][2] = 32 regs
// Per warp-k: 1 LDS.128 z (128B unique) + 1 LDS.128 es (64B unique) + 8 ffma2.
__global__ void __launch_bounds__(128, 4)
vq_main_kernel(const float* __restrict__ z, const float* __restrict__ emb,
               float* __restrict__ out)
{
    __shared__ __align__(16) float zs[DIM][PTSB];     // [k][pt]  8 KB
    __shared__ __align__(16) float es[2][DIM][CCH];   // [k][c] chunk, 32 KB
    __shared__ float zsq_s[PTSB];
    __shared__ unsigned long long red[16][PTSB];      // 4 KB
    __shared__ float warp_s[4];
    __shared__ int   last_s;

    const int tid  = threadIdx.x;
    const int pt_t = tid & 7;     // 0..7  point group (4 pts)
    const int cg   = tid >> 3;    // 0..15 code group (4 codes = 2 pairs)
    const int pt0  = blockIdx.x * PTSB;
    const int b    = pt0 >> 10;
    const int hw0  = pt0 & 1023;
    const float* zb = z + (size_t)b * BHW + hw0;

    // issue es chunk 0 fetch immediately (16 KB from transposed d_est)
    {
        unsigned int dst0 = (unsigned int)__cvta_generic_to_shared(&es[0][0][0]);
        #pragma unroll
        for (int i = 0; i < 8; ++i) {
            int f = i * 128 + tid;           // 16B unit 0..1023
            int k = f >> 4, c16 = f & 15;    // 16 units per k-row
            cpasync16(dst0 + (unsigned)(k * CCH + c16 * 4) * 4u,
                      &d_est[(size_t)k * NE + c16 * 4]);
        }
        CP_COMMIT();
    }

    // load z tile (coalesced), natural layout [k][pt]
    #pragma unroll
    for (int i = 0; i < 16; ++i) {
        int f = i * 128 + tid;
        int k = f >> 5, p = f & 31;
        zs[k][p] = zb[(size_t)k * HW + p];
    }

    // one-hot region head/tail scalars (base%4==2); float4 body interleaved below
    float* encb = out + OFF_ENC + (size_t)pt0 * NE;    // 32768 floats
    float4* e4  = (float4*)(encb + 2);                 // 8191 float4s
    if (tid == 0) {
        encb[0] = 0.f; encb[1] = 0.f;
        encb[32766] = 0.f; encb[32767] = 0.f;
    }
    __syncthreads();

    // per-point ||z||^2, sequential fp32 rn (matches reference rounding)
    if (tid < PTSB) {
        float s = 0.f;
        #pragma unroll
        for (int k = 0; k < DIM; ++k) {
            float v = zs[k][tid];
            s = __fadd_rn(s, __fmul_rn(v, v));
        }
        zsq_s[tid] = s;
    }

    unsigned long long best[4];
    #pragma unroll
    for (int p = 0; p < 4; ++p) best[p] = 0xFFFFFFFFFFFFFFFFULL;

    for (int h = 0; h < NCH; ++h) {
        const int buf = h & 1;
        CP_WAIT0();            // chunk h landed
        __syncthreads();       // visible; h-1 compute done (covers zsq_s on h=0)

        // prefetch chunk h+1 into the other buffer
        if (h + 1 < NCH) {
            unsigned int dstn = (unsigned int)__cvta_generic_to_shared(
                &es[buf ^ 1][0][0]);
            const float* src = d_est + (size_t)(h + 1) * CCH;
            #pragma unroll
            for (int i = 0; i < 8; ++i) {
                int f = i * 128 + tid;
                int k = f >> 4, c16 = f & 15;
                cpasync16(dstn + (unsigned)(k * CCH + c16 * 4) * 4u,
                          src + (size_t)k * NE + c16 * 4);
            }
        }
        CP_COMMIT();

        // interleaved one-hot zero-fill slice (drains under the FMAs)
        #pragma unroll
        for (int i = 0; i < 4; ++i) {
            int j = h * 512 + i * 128 + tid;
            if (j < 8191) e4[j] = make_float4(0.f, 0.f, 0.f, 0.f);
        }

        unsigned long long acc[4][2];      // [point][code-pair]
        #pragma unroll
        for (int p = 0; p < 4; ++p) { acc[p][0] = 0ULL; acc[p][1] = 0ULL; }

        #pragma unroll 8
        for (int k = 0; k < DIM; ++k) {
            float4 zv = *(const float4*)&zs[k][pt_t * 4];       // 1 LDS.128
            ull2   ep = *(const ull2*)&es[buf][k][cg * 4];      // 1 LDS.128
            unsigned long long z0 = pk2(zv.x), z1 = pk2(zv.y);
            unsigned long long z2 = pk2(zv.z), z3 = pk2(zv.w);
            ffma2(acc[0][0], z0, ep.a); ffma2(acc[0][1], z0, ep.b);
            ffma2(acc[1][0], z1, ep.a); ffma2(acc[1][1], z1, ep.b);
            ffma2(acc[2][0], z2, ep.a); ffma2(acc[2][1], z2, ep.b);
            ffma2(acc[3][0], z3, ep.a); ffma2(acc[3][1], z3, ep.b);
        }

        // distances + running argmin (u64 key -> first-index tie-break)
        const int cbase = h * CCH + cg * 4;
        #pragma unroll
        for (int j = 0; j < 2; ++j) {
            float esq0 = __ldg(&d_esq[cbase + 2 * j]);
            float esq1 = __ldg(&d_esq[cbase + 2 * j + 1]);
            #pragma unroll
            for (int p = 0; p < 4; ++p) {
                float zq2 = zsq_s[pt_t * 4 + p];
                float2 dot = upk(acc[p][j]);
                {
                    float d = __fadd_rn(__fadd_rn(zq2, esq0), -2.0f * dot.x);
                    unsigned long long k64 =
                        ((unsigned long long)ordf(d) << 32) | (unsigned)(cbase + 2 * j);
                    if (k64 < best[p]) best[p] = k64;
                }
                {
                    float d = __fadd_rn(__fadd_rn(zq2, esq1), -2.0f * dot.y);
                    unsigned long long k64 =
                        ((unsigned long long)ordf(d) << 32) | (unsigned)(cbase + 2 * j + 1);
                    if (k64 < best[p]) best[p] = k64;
                }
            }
        }
    }

    // cross-thread argmin reduction per point (16 code-groups per point)
    __syncthreads();
    #pragma unroll
    for (int p = 0; p < 4; ++p) red[cg][pt_t * 4 + p] = best[p];
    __syncthreads();

    if (tid < PTSB) {
        unsigned long long bk = red[0][tid];
        #pragma unroll
        for (int t = 1; t < 16; ++t) {
            unsigned long long v = red[t][tid];
            if (v < bk) bk = v;
        }
        int idx = (int)(unsigned int)bk;
        int n   = pt0 + tid;

        out[OFF_IDX + n] = (float)idx;
        atomicAdd(&d_count[idx], 1u);
        out[OFF_ENC + (unsigned long long)n * NE + (unsigned)idx] = 1.0f;

        // z_q gather + loss partial (straight-through: z_q_out == z_q in value)
        float errsum = 0.f;
        const float* er = emb + (size_t)idx * DIM;
        float* zq = out + OFF_ZQ + (size_t)b * BHW + hw0 + tid;
        #pragma unroll
        for (int c = 0; c < DIM; ++c) {
            float e  = __ldg(er + c);
            float zv = zs[c][tid];
            float df = e - zv;
            errsum   = fmaf(df, df, errsum);
            zq[(size_t)c * HW] = e;
        }
        #pragma unroll
        for (int o = 16; o > 0; o >>= 1)
            errsum += __shfl_down_sync(0xFFFFFFFFu, errsum, o);
        if (tid == 0) atomicAdd(&d_loss, errsum);
    }

    // ---------------- last-block finalize (perplexity + loss scalars) ----------------
    __threadfence();
    __syncthreads();
    if (tid == 0) last_s = (atomicAdd(&d_done, 1u) == NBLK - 1) ? 1 : 0;
    __syncthreads();
    if (last_s) {
        float part = 0.f;
        #pragma unroll
        for (int i = 0; i < 8; ++i) {
            int c = tid + i * 128;
            unsigned cnt = d_count[c];
            d_count[c] = 0u;                       // reset for graph replay
            float em = (float)cnt * (1.0f / 32768.0f);
            part += em * logf(em + 1e-10f);
        }
        #pragma unroll
        for (int o = 16; o > 0; o >>= 1)
            part += __shfl_down_sync(0xFFFFFFFFu, part, o);
        if ((tid & 31) == 0) warp_s[tid >> 5] = part;
        __syncthreads();
        if (tid == 0) {
            float w = warp_s[0] + warp_s[1] + warp_s[2] + warp_s[3];
            out[OFF_PERP] = expf(-w);
            out[OFF_LOSS] = 1.25f * d_loss * (1.0f / 2097152.0f);
            d_loss = 0.f;                          // reset for graph replay
            d_done = 0u;
        }
    }
}

// ---------------------------------------------------------------- launch
extern "C" void kernel_launch(void* const* d_in, const int* in_sizes, int n_in,
                              void* d_out, int out_size) {
    const float* z   = (const float*)d_in[0];
    const float* emb = (const float*)d_in[1];
    float*       out = (float*)d_out;

    prep_kernel<<<16, 128>>>(emb);
    vq_main_kernel<<<NBLK, 128>>>(z, emb, out);
}

// round 10
// speedup vs baseline: 1.1265x; 1.0477x over previous
#include <cuda_runtime.h>
#include <cstdint>

// Problem constants
#define NPTS   32768            // 32 * 32 * 32 points
#define DIM    64               // embedding dim
#define NE     1024             // codebook size
#define HW     1024             // 32*32 spatial
#define BHW    65536            // 64 channels * 1024 hw (per-batch stride in z)
#define PTSB   64               // points per block
#define CCH    128              // codes per chunk
#define NCH    8                // chunks
#define NBLK   (NPTS / PTSB)    // 512 blocks

// Output layout (flat concat of reference return tuple, float32):
// loss[1], z_q[2097152], perplexity[1], min_encodings[33554432], indices[32768]
#define OFF_LOSS 0ULL
#define OFF_ZQ   1ULL
#define OFF_PERP 2097153ULL
#define OFF_ENC  2097154ULL
#define OFF_IDX  35651586ULL

__device__ float        d_esq[NE];
__device__ float        d_est[DIM * NE];   // transposed codebook [k][c]
__device__ unsigned int d_count[NE];
__device__ float        d_loss = 0.f;
__device__ unsigned int d_done = 0u;

// ---------------------------------------------------------------- helpers
struct __align__(16) ull2 { unsigned long long a, b; };

static __device__ __forceinline__ unsigned long long pk2(float v) {
    unsigned long long r;
    asm("mov.b64 %0, {%1,%2};" : "=l"(r) : "f"(v), "f"(v));
    return r;
}
static __device__ __forceinline__ void ffma2(unsigned long long& d,
                                             unsigned long long a,
                                             unsigned long long b) {
    asm("fma.rn.f32x2 %0, %1, %2, %0;" : "+l"(d) : "l"(a), "l"(b));
}
static __device__ __forceinline__ float2 upk(unsigned long long v) {
    float2 f;
    asm("mov.b64 {%0,%1}, %2;" : "=f"(f.x), "=f"(f.y) : "l"(v));
    return f;
}
static __device__ __forceinline__ unsigned int ordf(float x) {
    unsigned int b = __float_as_uint(x);
    return b ^ (unsigned int)(((int)b >> 31) | 0x80000000);
}
static __device__ __forceinline__ void cpasync16(unsigned int dst_smem,
                                                 const void* src) {
    asm volatile("cp.async.ca.shared.global [%0], [%1], 16;"
                 :: "r"(dst_smem), "l"(src));
}
#define CP_COMMIT() asm volatile("cp.async.commit_group;" ::: "memory")
#define CP_WAIT0()  asm volatile("cp.async.wait_group 0;" ::: "memory")

// ---------------------------------------------------------------- prep
// 16 blocks x 128 threads; block handles 64 codes. Verified ~5.3us.
__global__ void prep_kernel(const float* __restrict__ emb) {
    __shared__ float sb[64][DIM + 1];
    const int tid = threadIdx.x;
    const int c0  = blockIdx.x * 64;

    const float4* src = (const float4*)(emb + (size_t)c0 * DIM);
    #pragma unroll
    for (int i = 0; i < 8; ++i) {
        int f  = i * 128 + tid;
        int c  = f >> 4;
        int k4 = f & 15;
        float4 v = src[f];
        sb[c][k4 * 4 + 0] = v.x;
        sb[c][k4 * 4 + 1] = v.y;
        sb[c][k4 * 4 + 2] = v.z;
        sb[c][k4 * 4 + 3] = v.w;
    }
    __syncthreads();

    if (tid < 64) {
        const int c = c0 + tid;
        float s = 0.f;
        #pragma unroll
        for (int k = 0; k < DIM; ++k) {
            float v = sb[tid][k];
            s = __fadd_rn(s, __fmul_rn(v, v));
            d_est[k * NE + c] = v;
        }
        d_esq[c]   = s;
        d_count[c] = 0u;
        if (c == 0) { d_loss = 0.f; d_done = 0u; }
    }
}

// ---------------------------------------------------------------- main fused kernel
// block: 128 threads = 8 pt-groups (pt_t) x 16 code-groups (cg, 8 codes)
// block tile: 64 points x 128 codes per chunk (8 chunks -> 1024 codes)
// thread tile: 8 points (4 NATURAL f32x2 pairs) x 8 codes (pk2-dup es)
//   per warp-k: 2 conflict-free LDS.128 (z) + 8 broadcast LDS.32 (es)
//   = 16 wavefronts vs 16 fma-cycles (32 ffma2)  ->  LDS:fma = 1:1
__global__ void __launch_bounds__(128, 2)
vq_main_kernel(const float* __restrict__ z, const float* __restrict__ emb,
               float* __restrict__ out)
{
    __shared__ __align__(16) float zs[DIM][PTSB];      // [k][pt] 16 KB
    __shared__ __align__(16) float es[2][DIM][CCH];    // [k][c] 2x32 KB
    __shared__ float zsq_s[PTSB];
    __shared__ unsigned long long red[16][PTSB];       // 8 KB
    __shared__ float warp_s[4];
    __shared__ int   last_s;

    const int tid  = threadIdx.x;
    const int pt_t = tid & 7;     // 0..7  point group (8 pts)
    const int cg   = tid >> 3;    // 0..15 code group (8 codes)
    const int pt0  = blockIdx.x * PTSB;
    const int b    = pt0 >> 10;
    const int hw0  = pt0 & 1023;
    const float* zb = z + (size_t)b * BHW + hw0;

    // issue es chunk 0 fetch immediately (32 KB from transposed d_est)
    {
        unsigned int dst0 = (unsigned int)__cvta_generic_to_shared(&es[0][0][0]);
        #pragma unroll
        for (int i = 0; i < 16; ++i) {
            int f = i * 128 + tid;           // 16B unit 0..2047
            int k = f >> 5, c16 = f & 31;    // 32 units per k-row
            cpasync16(dst0 + (unsigned)(k * CCH + c16 * 4) * 4u,
                      &d_est[(size_t)k * NE + c16 * 4]);
        }
        CP_COMMIT();
    }

    // load z tile (coalesced), natural layout [k][pt]
    #pragma unroll
    for (int i = 0; i < 32; ++i) {
        int f = i * 128 + tid;
        int k = f >> 6, p = f & 63;
        zs[k][p] = zb[(size_t)k * HW + p];
    }

    // one-hot region head/tail scalars (base%4==2); float4 body interleaved below
    float* encb = out + OFF_ENC + (size_t)pt0 * NE;    // 65536 floats
    float4* e4  = (float4*)(encb + 2);                 // 16383 float4s
    if (tid == 0) {
        encb[0] = 0.f; encb[1] = 0.f;
        encb[65534] = 0.f; encb[65535] = 0.f;
    }
    __syncthreads();

    // per-point ||z||^2, sequential fp32 rn (matches reference rounding)
    if (tid < PTSB) {
        float s = 0.f;
        #pragma unroll
        for (int k = 0; k < DIM; ++k) {
            float v = zs[k][tid];
            s = __fadd_rn(s, __fmul_rn(v, v));
        }
        zsq_s[tid] = s;
    }

    unsigned long long best[8];   // local point lp = pp*2 + (0|1)
    #pragma unroll
    for (int p = 0; p < 8; ++p) best[p] = 0xFFFFFFFFFFFFFFFFULL;

    for (int h = 0; h < NCH; ++h) {
        const int buf = h & 1;
        CP_WAIT0();            // chunk h landed
        __syncthreads();       // visible to all; h-1 compute done (covers zsq_s)

        // prefetch chunk h+1 into the other buffer (overlaps compute)
        if (h + 1 < NCH) {
            unsigned int dstn = (unsigned int)__cvta_generic_to_shared(
                &es[buf ^ 1][0][0]);
            const float* src = d_est + (size_t)(h + 1) * CCH;
            #pragma unroll
            for (int i = 0; i < 16; ++i) {
                int f = i * 128 + tid;
                int k = f >> 5, c16 = f & 31;
                cpasync16(dstn + (unsigned)(k * CCH + c16 * 4) * 4u,
                          src + (size_t)k * NE + c16 * 4);
            }
        }
        CP_COMMIT();

        // interleaved one-hot zero-fill slice (drains under the FMAs)
        #pragma unroll
        for (int i = 0; i < 16; ++i) {
            int j = h * 2048 + i * 128 + tid;
            if (j < 16383) e4[j] = make_float4(0.f, 0.f, 0.f, 0.f);
        }

        unsigned long long acc[4][8];      // [point-pair][code]
        #pragma unroll
        for (int pp = 0; pp < 4; ++pp)
            #pragma unroll
            for (int j = 0; j < 8; ++j) acc[pp][j] = 0ULL;

        #pragma unroll 4
        for (int k = 0; k < DIM; ++k) {
            // 4 natural point-pairs: points pt_t*4..+3 and 32+pt_t*4..+3
            ull2 zA = *(const ull2*)&zs[k][pt_t * 4];        // pairs 0,1
            ull2 zB = *(const ull2*)&zs[k][32 + pt_t * 4];   // pairs 2,3
            const float* ek = &es[buf][k][cg * 8];
            #pragma unroll
            for (int j = 0; j < 8; ++j) {
                unsigned long long ed = pk2(ek[j]);          // {e,e}
                ffma2(acc[0][j], zA.a, ed);
                ffma2(acc[1][j], zA.b, ed);
                ffma2(acc[2][j], zB.a, ed);
                ffma2(acc[3][j], zB.b, ed);
            }
        }

        // distances + running argmin (u64 key -> first-index tie-break)
        const int cbase = h * CCH + cg * 8;
        #pragma unroll
        for (int j = 0; j < 8; ++j) {
            float esq = __ldg(&d_esq[cbase + j]);
            unsigned code = (unsigned)(cbase + j);
            #pragma unroll
            for (int pp = 0; pp < 4; ++pp) {
                int pbase = (pp >> 1) * 32 + pt_t * 4 + (pp & 1) * 2;
                float2 dot = upk(acc[pp][j]);
                {
                    float zq2 = zsq_s[pbase];
                    float d = __fadd_rn(__fadd_rn(zq2, esq), -2.0f * dot.x);
                    unsigned long long k64 =
                        ((unsigned long long)ordf(d) << 32) | code;
                    if (k64 < best[pp * 2]) best[pp * 2] = k64;
                }
                {
                    float zq2 = zsq_s[pbase + 1];
                    float d = __fadd_rn(__fadd_rn(zq2, esq), -2.0f * dot.y);
                    unsigned long long k64 =
                        ((unsigned long long)ordf(d) << 32) | code;
                    if (k64 < best[pp * 2 + 1]) best[pp * 2 + 1] = k64;
                }
            }
        }
    }

    // cross-thread argmin reduction per point
    __syncthreads();
    #pragma unroll
    for (int pp = 0; pp < 4; ++pp) {
        int pbase = (pp >> 1) * 32 + pt_t * 4 + (pp & 1) * 2;
        red[cg][pbase]     = best[pp * 2];
        red[cg][pbase + 1] = best[pp * 2 + 1];
    }
    __syncthreads();

    if (tid < PTSB) {
        unsigned long long bk = red[0][tid];
        #pragma unroll
        for (int t = 1; t < 16; ++t) {
            unsigned long long v = red[t][tid];
            if (v < bk) bk = v;
        }
        int idx = (int)(unsigned int)bk;
        int n   = pt0 + tid;

        out[OFF_IDX + n] = (float)idx;
        atomicAdd(&d_count[idx], 1u);
        out[OFF_ENC + (unsigned long long)n * NE + (unsigned)idx] = 1.0f;

        // z_q gather + loss partial (straight-through: z_q_out == z_q in value)
        float errsum = 0.f;
        const float* er = emb + (size_t)idx * DIM;
        float* zq = out + OFF_ZQ + (size_t)b * BHW + hw0 + tid;
        #pragma unroll
        for (int c = 0; c < DIM; ++c) {
            float e  = __ldg(er + c);
            float zv = zs[c][tid];
            float df = e - zv;
            errsum   = fmaf(df, df, errsum);
            zq[(size_t)c * HW] = e;
        }
        #pragma unroll
        for (int o = 16; o > 0; o >>= 1)
            errsum += __shfl_down_sync(0xFFFFFFFFu, errsum, o);
        if ((tid & 31) == 0) atomicAdd(&d_loss, errsum);
    }

    // ---------------- last-block finalize (perplexity + loss scalars) ----------------
    __threadfence();
    __syncthreads();
    if (tid == 0) last_s = (atomicAdd(&d_done, 1u) == NBLK - 1) ? 1 : 0;
    __syncthreads();
    if (last_s) {
        float part = 0.f;
        #pragma unroll
        for (int i = 0; i < 8; ++i) {
            int c = tid + i * 128;
            unsigned cnt = d_count[c];
            d_count[c] = 0u;                       // reset for graph replay
            float em = (float)cnt * (1.0f / 32768.0f);
            part += em * logf(em + 1e-10f);
        }
        #pragma unroll
        for (int o = 16; o > 0; o >>= 1)
            part += __shfl_down_sync(0xFFFFFFFFu, part, o);
        if ((tid & 31) == 0) warp_s[tid >> 5] = part;
        __syncthreads();
        if (tid == 0) {
            float w = warp_s[0] + warp_s[1] + warp_s[2] + warp_s[3];
            out[OFF_PERP] = expf(-w);
            out[OFF_LOSS] = 1.25f * d_loss * (1.0f / 2097152.0f);
            d_loss = 0.f;                          // reset for graph replay
            d_done = 0u;
        }
    }
}

// ---------------------------------------------------------------- launch
extern "C" void kernel_launch(void* const* d_in, const int* in_sizes, int n_in,
                              void* d_out, int out_size) {
    const float* z   = (const float*)d_in[0];
    const float* emb = (const float*)d_in[1];
    float*       out = (float*)d_out;

    prep_kernel<<<16, 128>>>(emb);
    vq_main_kernel<<<NBLK, 128>>>(z, emb, out);
}